// round 16
// baseline (speedup 1.0000x reference)
#include <cuda_runtime.h>
#include <cstdint>

#define C 128
#define HH 320
#define WW 320
#define BB 2
#define SEG 80
#define NBLK (BB*HH*(WW/SEG))   // 2560
#define NTH 320

typedef unsigned long long u64;

// ---------------- device scratch ----------------
// g_WA2: A matrix (160 rows x 256 k), tf32-rounded, fragment-packed:
// index (((c*4 + t)*40) + mh*8 + g)*8 + jm + 4*half  <-  A[m][k],
//   m = 32*mh + g + 8*jm, k = 8*c + t + 4*half.
// Each thread's per-chunk fragment = 32 contiguous bytes.
__device__ __align__(16) float g_WA2[256*160];
__device__ __align__(16) float g_dm2t[32*C];    // [j][c] = dm2[c][j]

// ---------------- helpers ----------------
__device__ __forceinline__ u64 splat2(float w) {
    u64 r; unsigned u = __float_as_uint(w);
    asm("mov.b64 %0, {%1, %1};" : "=l"(r) : "r"(u));
    return r;
}
__device__ __forceinline__ u64 pack2(float a, float b) {
    u64 r;
    asm("mov.b64 %0, {%1, %2};" : "=l"(r) : "r"(__float_as_uint(a)), "r"(__float_as_uint(b)));
    return r;
}
__device__ __forceinline__ void unpack2(u64 v, float& a, float& b) {
    unsigned x, y; asm("mov.b64 {%0, %1}, %2;" : "=r"(x), "=r"(y) : "l"(v));
    a = __uint_as_float(x); b = __uint_as_float(y);
}
__device__ __forceinline__ u64 ffma2(u64 a, u64 b, u64 c) {
    u64 d;
    asm("fma.rn.f32x2 %0, %1, %2, %3;" : "=l"(d) : "l"(a), "l"(b), "l"(c));
    return d;
}
__device__ __forceinline__ float lrelu(float v) { return v > 0.f ? v : 0.1f * v; }
__device__ __forceinline__ float tf32r(float v) {
    uint32_t t; asm("cvt.rna.tf32.f32 %0, %1;" : "=r"(t) : "f"(v));
    return __uint_as_float(t);
}
__device__ __forceinline__ void mma_tf32(float* c, uint32_t a0, uint32_t a1, uint32_t a2, uint32_t a3,
                                         uint32_t b0, uint32_t b1) {
    asm volatile("mma.sync.aligned.m16n8k8.row.col.f32.tf32.tf32.f32 "
        "{%0,%1,%2,%3}, {%4,%5,%6,%7}, {%8,%9}, {%0,%1,%2,%3};"
        : "+f"(c[0]), "+f"(c[1]), "+f"(c[2]), "+f"(c[3])
        : "r"(a0), "r"(a1), "r"(a2), "r"(a3), "r"(b0), "r"(b1));
}

// ---------------- fold kernel ----------------
// Block k: col k of W_H=fuse_H@pwh, W_V=fuse_V@pwv, plus dm1-folded rows; tf32 -> g_WA2.
#define SMEM_FOLD ((128*129*2 + 32*129 + 4*128) * 4)
__global__ void __launch_bounds__(256) k_fold(
    const float* __restrict__ wf,   // [128][256]
    const float* __restrict__ pwh,  // [128][128]
    const float* __restrict__ pwv,  // [128][128]
    const float* __restrict__ dm1,  // [32][128]
    const float* __restrict__ dm2)  // [128][32]
{
    extern __shared__ float s[];
    float* FU = s;              // fuse_H [128][129]
    float* FV = s + 16512;      // fuse_V [128][129]
    float* D1 = s + 33024;      // dm1 [32][129]
    float* cH = s + 37152;      // [128] pw col, later dH
    float* cV = cH + 128;
    float* wH = cV + 128;       // [128]
    float* wV = wH + 128;
    const int k = blockIdx.x;
    const int tid = threadIdx.x;

    for (int i = tid; i < 128*128; i += 256) {
        int m = i >> 7, c = i & 127;
        FU[m*129 + c] = wf[m*256 + c];
        FV[m*129 + c] = wf[m*256 + 128 + c];
    }
    for (int i = tid; i < 32*128; i += 256)
        D1[(i >> 7)*129 + (i & 127)] = dm1[i];
    if (tid < 128) { cH[tid] = pwh[tid*128 + k]; cV[tid] = pwv[tid*128 + k]; }
    __syncthreads();

    {   // wH[m] = dot(fuse_H[m][:], pwh[:,k]); wV likewise
        int m = tid & 127;
        bool v = tid >= 128;
        const float* row = (v ? FV : FU) + m*129;
        const float* col = v ? cV : cH;
        float a = 0.f;
        #pragma unroll 8
        for (int c = 0; c < 128; ++c) a = fmaf(row[c], col[c], a);
        (v ? wV : wH)[m] = a;
    }
    __syncthreads();

    if (tid < 64) {  // dH[j] = dot(dm1[j][:], wH[:])
        int j = tid & 31;
        int t = tid >> 5;
        const float* w = t ? wV : wH;
        float a = 0.f;
        #pragma unroll 8
        for (int m = 0; m < 128; ++m) a = fmaf(D1[j*129 + m], w[m], a);
        (t ? cV : cH)[j] = a;
    }
    __syncthreads();

    for (int i = tid; i < 2*160; i += 256) {
        int t = i / 160, r = i - t*160;
        float val = (r < 128) ? (t ? wV : wH)[r] : (t ? cV : cH)[r - 128];
        int kc   = t*128 + k;
        int cck  = kc >> 3, kk = kc & 7, tt = kk & 3, half = kk >> 2;
        int mh   = r >> 5,  g  = r & 7,  jm = (r & 31) >> 3;
        g_WA2[(size_t)((cck*4 + tt)*40 + mh*8 + g)*8 + jm + 4*half] = tf32r(val);
    }
    if (k == 0) {
        for (int i = tid; i < 128*32; i += 256) {
            int c = i >> 5, j = i & 31;
            g_dm2t[j*128 + c] = dm2[c*32 + j];
        }
    }
}

// ---------------- main fused kernel ----------------
// grid 2560 = 640 rows x 4 segments of 80; 320 threads; occ 2.
// smem floats: Tm[0,22528) [256][88]; dwhs[22528,23168); dwvs[23168,23808)
// overlays after GEMM: Esm [128][84] at 0, Usm [32][88] at 10752.
#define SMEM_MAIN (23808 * 4)

__global__ void __launch_bounds__(NTH, 2) k_main(
    const float* __restrict__ x,
    const float* __restrict__ dwh,      // [128][5]
    const float* __restrict__ dwv,      // [128][5]
    const float* __restrict__ scale_p,
    float* __restrict__ out)
{
    extern __shared__ float sm[];
    float* Tm   = sm;             // [256][88]
    float* dwhs = sm + 22528;
    float* dwvs = sm + 23168;
    float* Esm  = sm;             // overlay [c][p] stride 84
    float* Usm  = sm + 10752;     // overlay [j][p] stride 88

    const int tid  = threadIdx.x;
    const int lane = tid & 31;
    const int wrp  = tid >> 5;
    const int bx   = blockIdx.x;
    const int seg  = bx & 3;
    const int row  = bx >> 2;
    const int b    = row / HH;
    const int y    = row - b * HH;
    const int ai   = y % 5;
    const int y0   = y - ai;
    const int x0   = seg * SEG;

    // warp tile ids (GEMM): mh = warp row-band (0..4), nh = col-half (0..1)
    const int mh  = wrp % 5;
    const int nh  = wrp / 5;
    const int gid = lane >> 2;     // 0..7
    const int tig = lane & 3;      // 0..3

    // ---- A fragment prefetch (chunk 0) issued before stage 1 ----
    const float4* gA = (const float4*)g_WA2;
    const int abase = (tig*40 + mh*8 + gid) * 2;    // float4 index; +320 per chunk
    float4 q0n = __ldg(gA + abase);
    float4 q1n = __ldg(gA + abase + 1);

    for (int i = tid; i < 640; i += NTH) { dwhs[i] = dwh[i]; dwvs[i] = dwv[i]; }
    __syncthreads();

    // ---- stage 1: depthwise convs + lrelu -> Tm (tf32), pixel pairs ----
    const float* xb = x + (size_t)b * C * HH * WW;
    #pragma unroll 2
    for (int it = 0; it < 16; ++it) {
        int i  = tid + NTH * it;      // 0..5119
        int k  = i / 40;
        int pp = i - k * 40;
        int p0 = pp * 2;
        const float* xrow0 = xb + ((size_t)k * HH + y0) * WW + x0 + p0;
        const float* xr    = xb + ((size_t)k * HH + y)  * WW + x0 + p0;
        float2 v0 = *(const float2*)(xrow0);
        float2 v1 = *(const float2*)(xrow0 + WW);
        float2 v2 = *(const float2*)(xrow0 + 2*WW);
        float2 v3 = *(const float2*)(xrow0 + 3*WW);
        float2 v4 = *(const float2*)(xrow0 + 4*WW);
        // vertical (packed)
        u64 vr2[5] = { pack2(v0.x, v0.y), pack2(v1.x, v1.y), pack2(v2.x, v2.y),
                       pack2(v3.x, v3.y), pack2(v4.x, v4.y) };
        const float* wv = dwvs + k*5;
        u64 tvp = 0ull;
        #pragma unroll
        for (int r = 0; r < 5; ++r) {
            int q = r - ai + 2;
            if ((unsigned)q < 5u) tvp = ffma2(splat2(wv[q]), vr2[r], tvp);
        }
        // horizontal
        float2 c2 = (ai == 0) ? v0 : (ai == 1) ? v1 : (ai == 2) ? v2 : (ai == 3) ? v3 : v4;
        float2 mld = make_float2(0.f, 0.f), pld = make_float2(0.f, 0.f);
        if (p0 > 0)  mld = *(const float2*)(xr - 2);
        if (p0 < 78) pld = *(const float2*)(xr + 2);
        const float* wh = dwhs + k*5;
        float w0 = wh[0], w1 = wh[1], w2h = wh[2], w3 = wh[3], w4 = wh[4];
        int aj0 = p0 % 5;
        int aj1 = aj0 + 1; if (aj1 == 5) aj1 = 0;
        float th0 = w2h * c2.x;
        if (aj0 >= 2) th0 = fmaf(w0, mld.x, th0);
        if (aj0 >= 1) th0 = fmaf(w1, mld.y, th0);
        if (aj0 <= 3) th0 = fmaf(w3, c2.y, th0);
        if (aj0 <= 2) th0 = fmaf(w4, pld.x, th0);
        float th1 = w2h * c2.y;
        if (aj1 >= 2) th1 = fmaf(w0, mld.y, th1);
        if (aj1 >= 1) th1 = fmaf(w1, c2.x, th1);
        if (aj1 <= 3) th1 = fmaf(w3, pld.x, th1);
        if (aj1 <= 2) th1 = fmaf(w4, pld.y, th1);

        float tv0, tv1; unpack2(tvp, tv0, tv1);
        *(float2*)(Tm + k*88 + p0)         = make_float2(tf32r(lrelu(th0)), tf32r(lrelu(th1)));
        *(float2*)(Tm + (128 + k)*88 + p0) = make_float2(tf32r(lrelu(tv0)), tf32r(lrelu(tv1)));
    }
    __syncthreads();

    // ---- GEMM via HMMA tf32: [160][80] = A @ T, no in-loop barriers ----
    float acc[2][5][4];
    #pragma unroll
    for (int i = 0; i < 2; ++i)
        #pragma unroll
        for (int t = 0; t < 5; ++t)
            #pragma unroll
            for (int q = 0; q < 4; ++q) acc[i][t][q] = 0.f;

    #pragma unroll 1
    for (int c = 0; c < 32; ++c) {
        float4 q0 = q0n, q1 = q1n;
        if (c < 31) {
            q0n = __ldg(gA + abase + (c + 1)*320);
            q1n = __ldg(gA + abase + (c + 1)*320 + 1);
        }
        const float* b0p = Tm + (8*c + tig)*88 + 40*nh + gid;
        const float* b1p = b0p + 4*88;
        #pragma unroll
        for (int t = 0; t < 5; ++t) {
            uint32_t b0 = __float_as_uint(b0p[8*t]);
            uint32_t b1 = __float_as_uint(b1p[8*t]);
            mma_tf32(acc[0][t], __float_as_uint(q0.x), __float_as_uint(q0.y),
                                __float_as_uint(q1.x), __float_as_uint(q1.y), b0, b1);
            mma_tf32(acc[1][t], __float_as_uint(q0.z), __float_as_uint(q0.w),
                                __float_as_uint(q1.z), __float_as_uint(q1.w), b0, b1);
        }
    }
    __syncthreads();   // done reading Tm before overlaying Esm/Usm

    // ---- scatter: epi rows -> Esm, dm1-folded rows (mh==4) -> lrelu -> Usm ----
    #pragma unroll
    for (int i = 0; i < 2; ++i) {
        int r = 32*mh + 16*i + gid;
        #pragma unroll
        for (int t = 0; t < 5; ++t) {
            int col = 40*nh + 8*t + 2*tig;
            if (mh < 4) {
                *(float2*)(Esm + r*84 + col)       = make_float2(acc[i][t][0], acc[i][t][1]);
                *(float2*)(Esm + (r + 8)*84 + col) = make_float2(acc[i][t][2], acc[i][t][3]);
            } else {
                int j = r - 128;
                *(float2*)(Usm + j*88 + col)       = make_float2(lrelu(acc[i][t][0]), lrelu(acc[i][t][1]));
                *(float2*)(Usm + (j + 8)*88 + col) = make_float2(lrelu(acc[i][t][2]), lrelu(acc[i][t][3]));
            }
        }
    }
    __syncthreads();

    // ---- dm2 @ u -> sigmoid gate; out = x + scl * epi * gate ----
    const int pq = tid % 10;      // 10 groups of 8 pixels
    const int cg = tid / 10;      // 32 groups of 4 channels
    const int c0 = cg * 4;
    const int q0p = pq * 8;
    u64 a2[4][4];
    #pragma unroll
    for (int i = 0; i < 4; ++i)
        #pragma unroll
        for (int s = 0; s < 4; ++s) a2[i][s] = 0ull;

    #pragma unroll 4
    for (int j = 0; j < 32; ++j) {
        float4 w = __ldg((const float4*)(g_dm2t + j*128 + c0));
        u64 w2[4] = { splat2(w.x), splat2(w.y), splat2(w.z), splat2(w.w) };
        ulonglong2 ua = *(const ulonglong2*)(Usm + j*88 + q0p);
        ulonglong2 ub = *(const ulonglong2*)(Usm + j*88 + q0p + 4);
        u64 up[4] = { ua.x, ua.y, ub.x, ub.y };
        #pragma unroll
        for (int i = 0; i < 4; ++i)
            #pragma unroll
            for (int s = 0; s < 4; ++s) a2[i][s] = ffma2(w2[i], up[s], a2[i][s]);
    }

    const float scl = scale_p[0];
    #pragma unroll
    for (int i = 0; i < 4; ++i) {
        int c = c0 + i;
        size_t base = ((size_t)(b*C + c) * HH + y) * WW + x0 + q0p;
        #pragma unroll
        for (int s = 0; s < 4; ++s) {
            float s0, s1;
            unpack2(a2[i][s], s0, s1);
            float d0 = __frcp_rn(1.f + __expf(-s0));
            float d1 = __frcp_rn(1.f + __expf(-s1));
            float e0, e1;
            unpack2(*(const u64*)(Esm + c*84 + q0p + 2*s), e0, e1);
            float2 xv = *(const float2*)(x + base + 2*s);
            float2 o;
            o.x = fmaf(scl * d0, e0, xv.x);
            o.y = fmaf(scl * d1, e1, xv.y);
            *(float2*)(out + base + 2*s) = o;
        }
    }
}

// ---------------- launch ----------------
extern "C" void kernel_launch(void* const* d_in, const int* in_sizes, int n_in,
                              void* d_out, int out_size) {
    (void)in_sizes; (void)n_in; (void)out_size;
    const float* x      = (const float*)d_in[0];
    const float* w_h_dw = (const float*)d_in[1];
    const float* w_h_pw = (const float*)d_in[2];
    const float* w_v_dw = (const float*)d_in[3];
    const float* w_v_pw = (const float*)d_in[4];
    const float* w_dm1  = (const float*)d_in[5];
    const float* w_dm2  = (const float*)d_in[6];
    const float* w_fuse = (const float*)d_in[7];
    const float* scale  = (const float*)d_in[8];
    float* out = (float*)d_out;

    cudaFuncSetAttribute(k_fold, cudaFuncAttributeMaxDynamicSharedMemorySize, SMEM_FOLD);
    cudaFuncSetAttribute(k_main, cudaFuncAttributeMaxDynamicSharedMemorySize, SMEM_MAIN);

    k_fold<<<128, 256, SMEM_FOLD>>>(w_fuse, w_h_pw, w_v_pw, w_dm1, w_dm2);
    k_main<<<NBLK, NTH, SMEM_MAIN>>>(x, w_h_dw, w_v_dw, scale, out);
}